// round 16
// baseline (speedup 1.0000x reference)
#include <cuda_runtime.h>
#include <cuda_fp16.h>
#include <cstdint>
#include <cstddef>

// ---------------------------------------------------------------------------
// Problem constants
// ---------------------------------------------------------------------------
#define BB      8
#define LL      1024
#define DM      512
#define DI      1024
#define NSTATE  16
#define RK      32
#define NT      (BB*LL)          // 8192 tokens
#define DEPTH   4

// ---------------------------------------------------------------------------
// Scratch buffers
// ---------------------------------------------------------------------------
__device__ float  g_resid[NT*DM];
__device__ __half g_h    [NT*DM];
__device__ __half g_xz   [NT*2*DI];
__device__ __half g_xc   [2*NT*DI];
__device__ float  g_xdbl [2*NT*64];
__device__ __half g_y    [2*NT*DI];
__device__ __half g_o    [2*NT*DM];
__device__ __half g_w1[DEPTH*2*DI*DM];
__device__ __half g_w2[DEPTH*64*DI];
__device__ __half g_w4[DEPTH*DM*DI];

// ---------------------------------------------------------------------------
// Helpers
// ---------------------------------------------------------------------------
__device__ __forceinline__ uint32_t smem_u32(const void* p){
    uint32_t a;
    asm("{ .reg .u64 t; cvta.to.shared.u64 t, %1; cvt.u32.u64 %0, t; }" : "=r"(a) : "l"(p));
    return a;
}
__device__ __forceinline__ float warpReduceSum(float v){
#pragma unroll
    for (int o=16;o>0;o>>=1) v += __shfl_xor_sync(0xffffffffu, v, o);
    return v;
}
__device__ __forceinline__ float silu_fast(float x){
    return x / (1.f + __expf(-x));
}
__device__ __forceinline__ void ldm_x4(uint32_t* r, uint32_t addr){
    asm volatile("ldmatrix.sync.aligned.m8n8.x4.shared.b16 {%0,%1,%2,%3}, [%4];"
        : "=r"(r[0]), "=r"(r[1]), "=r"(r[2]), "=r"(r[3]) : "r"(addr));
}
__device__ __forceinline__ void mma_f16(float* c, const uint32_t* a, const uint32_t* b){
    asm volatile(
        "mma.sync.aligned.m16n8k16.row.col.f32.f16.f16.f32 "
        "{%0,%1,%2,%3}, {%4,%5,%6,%7}, {%8,%9}, {%0,%1,%2,%3};"
        : "+f"(c[0]), "+f"(c[1]), "+f"(c[2]), "+f"(c[3])
        : "r"(a[0]), "r"(a[1]), "r"(a[2]), "r"(a[3]), "r"(b[0]), "r"(b[1]));
}
__device__ __forceinline__ void cp_async16(uint32_t dst, const void* src){
    asm volatile("cp.async.cg.shared.global [%0], [%1], 16;" :: "r"(dst), "l"(src));
}
__device__ __forceinline__ void cp_commit(){
    asm volatile("cp.async.commit_group;");
}
template<int N>
__device__ __forceinline__ void cp_wait(){
    asm volatile("cp.async.wait_group %0;" :: "n"(N));
}
__device__ __forceinline__ uint32_t pack_h2(__half a, __half b){
    __half2 h = __halves2half2(a, b);
    return *reinterpret_cast<uint32_t*>(&h);
}
__device__ __forceinline__ uint32_t swz(int r, int q){
    return (uint32_t)(r*64 + ((q ^ ((r>>1)&3))<<4));
}

// ---------------------------------------------------------------------------
// Weight conversion: fp32 -> single fp16 plane
// ---------------------------------------------------------------------------
__global__ void __launch_bounds__(256) wcvt_kernel(
    const float* __restrict__ src, __half* __restrict__ dst, int n4)
{
    const int i = blockIdx.x*256 + threadIdx.x;
    if (i >= n4) return;
    float4 v = reinterpret_cast<const float4*>(src)[i];
    uint2 o;
    o.x = pack_h2(__float2half_rn(v.x), __float2half_rn(v.y));
    o.y = pack_h2(__float2half_rn(v.z), __float2half_rn(v.w));
    reinterpret_cast<uint2*>(dst)[i] = o;
}

// ---------------------------------------------------------------------------
// LayerNorm + residual (+ fused bidirectional add of fp16 o); h as fp16.
// ---------------------------------------------------------------------------
__global__ void __launch_bounds__(128) ln_kernel(
    const float* __restrict__ src0, const __half* __restrict__ o,
    float* __restrict__ resid,
    const float* __restrict__ w, const float* __restrict__ b,
    __half* __restrict__ hout)
{
    __shared__ float sm[8];
    const int row = blockIdx.x, tid = threadIdx.x;
    float4 v = reinterpret_cast<const float4*>(src0 + (size_t)row*DM)[tid];
    if (o){
        const int t    = row & (LL-1);
        const int tokb = (row - t) + (LL-1 - t);
        uint2 a1 = reinterpret_cast<const uint2*>(o + (size_t)row*DM)[tid];
        uint2 a2 = reinterpret_cast<const uint2*>(o + (size_t)(NT + tokb)*DM)[tid];
        float2 f10 = __half22float2(*reinterpret_cast<__half2*>(&a1.x));
        float2 f11 = __half22float2(*reinterpret_cast<__half2*>(&a1.y));
        float2 f20 = __half22float2(*reinterpret_cast<__half2*>(&a2.x));
        float2 f21 = __half22float2(*reinterpret_cast<__half2*>(&a2.y));
        v.x += f10.x+f20.x; v.y += f10.y+f20.y;
        v.z += f11.x+f21.x; v.w += f11.y+f21.y;
    }
    reinterpret_cast<float4*>(resid + (size_t)row*DM)[tid] = v;

    float s = v.x+v.y+v.z+v.w;
    s = warpReduceSum(s);
    const int wid = tid>>5, lane = tid&31;
    if (lane==0) sm[wid]=s;
    __syncthreads();
    const float mu = (sm[0]+sm[1]+sm[2]+sm[3]) * (1.f/(float)DM);
    const float dx=v.x-mu, dy=v.y-mu, dz=v.z-mu, dw=v.w-mu;
    float q = dx*dx+dy*dy+dz*dz+dw*dw;
    q = warpReduceSum(q);
    if (lane==0) sm[4+wid]=q;
    __syncthreads();
    const float var = (sm[4]+sm[5]+sm[6]+sm[7]) * (1.f/(float)DM);
    const float rs = rsqrtf(var + 1e-5f);
    const float4 wv = reinterpret_cast<const float4*>(w)[tid];
    const float4 bv = reinterpret_cast<const float4*>(b)[tid];
    float4 ov;
    ov.x = dx*rs*wv.x + bv.x;
    ov.y = dy*rs*wv.y + bv.y;
    ov.z = dz*rs*wv.z + bv.z;
    ov.w = dw*rs*wv.w + bv.w;
    uint2 H;
    H.x = pack_h2(__float2half_rn(ov.x), __float2half_rn(ov.y));
    H.y = pack_h2(__float2half_rn(ov.z), __float2half_rn(ov.w));
    reinterpret_cast<uint2*>(hout + (size_t)row*DM)[tid] = H;
}

// ---------------------------------------------------------------------------
// fp16 MMA GEMM: C = A @ W^T. 128 threads, 4 warps 2x2, warp (BM/2)x(BN/2).
// STAGES-deep cp.async ring (STAGES-1 chunk prefetch), one barrier per chunk.
// STAGES=6 => 96KB smem => exactly 2 CTAs/SM on the big GEMMs (wave shaping).
// ---------------------------------------------------------------------------
template<int BM,int BN,int STAGES,typename OT>
__global__ void __launch_bounds__(128) gemm_f16_kernel(
    const __half* __restrict__ A, int lda,
    const __half* __restrict__ W, int K,
    OT* __restrict__ C, int ldc)
{
    constexpr int WM  = BM/2;
    constexpr int WN  = BN/2;
    constexpr int MT  = WM/16;
    constexpr int NTL = WN/8;
    constexpr int BOF = BM*64;
    constexpr int STAGE = BM*64 + BN*64;

    extern __shared__ __align__(16) char smem[];
    const uint32_t sb = smem_u32(smem);

    const int tid  = threadIdx.x;
    const int wid  = tid>>5, lane = tid&31;
    const int m0   = blockIdx.y*BM, n0 = blockIdx.x*BN;
    const int wm0  = (wid>>1)*WM;
    const int wn0  = (wid&1)*WN;

    float acc[MT][NTL][4];
#pragma unroll
    for (int i=0;i<MT;i++)
#pragma unroll
        for (int j=0;j<NTL;j++)
#pragma unroll
            for (int q=0;q<4;q++) acc[i][j][q]=0.f;

    const int a_row = (lane&7) + ((lane>>3)&1)*8;
    const int aq    = lane>>4;
    const int b_row = (lane&7) + (lane>>4)*8;
    const int bq    = (lane>>3)&1;

    auto issue_stage = [&](int s, int k0){
        const uint32_t base = sb + (uint32_t)(s*STAGE);
#pragma unroll
        for (int u=0; u<BM/32; ++u){
            const int id = tid + u*128;
            const int r = id>>2, q = id&3;
            cp_async16(base + swz(r,q), A + (size_t)(m0+r)*lda + k0 + q*8);
        }
#pragma unroll
        for (int u=0; u<BN/32; ++u){
            const int id = tid + u*128;
            const int r = id>>2, q = id&3;
            cp_async16(base + BOF + swz(r,q), W + (size_t)(n0+r)*K + k0 + q*8);
        }
        cp_commit();
    };

    const int nchunk = K >> 5;
    constexpr int PF = STAGES - 1;     // prefetch depth
#pragma unroll
    for (int s=0; s<PF; ++s)
        if (s < 32) issue_stage(s, s*32);   // nchunk >= 16 always here

    for (int c=0; c<nchunk; ++c){
        const int committed = (c+PF-1 < nchunk-1) ? (c+PF-1) : (nchunk-1);
        const int k = committed - c;
        if      (k >= 5) cp_wait<5>();
        else if (k == 4) cp_wait<4>();
        else if (k == 3) cp_wait<3>();
        else if (k == 2) cp_wait<2>();
        else if (k == 1) cp_wait<1>();
        else             cp_wait<0>();
        __syncthreads();
        if (c+PF < nchunk) issue_stage((c+PF)%STAGES, (c+PF)*32);

        const uint32_t sbs = sb + (uint32_t)((c%STAGES)*STAGE);
#pragma unroll
        for (int ks=0; ks<2; ++ks){
            uint32_t ah[MT][4];
#pragma unroll
            for (int mt=0; mt<MT; ++mt){
                const int row = wm0 + mt*16 + a_row;
                ldm_x4(ah[mt], sbs + swz(row, ks*2 + aq));
            }
            uint32_t bh[NTL][2];
#pragma unroll
            for (int tp=0; tp<NTL/2; ++tp){
                const int row = wn0 + tp*16 + b_row;
                uint32_t t4[4];
                ldm_x4(t4, sbs + BOF + swz(row, ks*2 + bq));
                bh[tp*2][0]=t4[0]; bh[tp*2][1]=t4[1];
                bh[tp*2+1][0]=t4[2]; bh[tp*2+1][1]=t4[3];
            }
#pragma unroll
            for (int mt=0; mt<MT; ++mt)
#pragma unroll
                for (int nt=0; nt<NTL; ++nt)
                    mma_f16(acc[mt][nt], ah[mt], bh[nt]);
        }
    }

    const int cr = lane>>2;
    const int cc = (lane&3)*2;
#pragma unroll
    for (int mt=0; mt<MT; ++mt){
        const int rbase = m0 + wm0 + mt*16 + cr;
#pragma unroll
        for (int nt=0; nt<NTL; ++nt){
            const int col = n0 + wn0 + nt*8 + cc;
            if (sizeof(OT) == 2){
                __half* Ch = reinterpret_cast<__half*>(C);
                uint32_t p0 = pack_h2(__float2half_rn(acc[mt][nt][0]),
                                      __float2half_rn(acc[mt][nt][1]));
                uint32_t p1 = pack_h2(__float2half_rn(acc[mt][nt][2]),
                                      __float2half_rn(acc[mt][nt][3]));
                *reinterpret_cast<uint32_t*>(Ch + (size_t)rbase*ldc + col)     = p0;
                *reinterpret_cast<uint32_t*>(Ch + (size_t)(rbase+8)*ldc + col) = p1;
            } else {
                float* Cf = reinterpret_cast<float*>(C);
                float2 v0; v0.x = acc[mt][nt][0]; v0.y = acc[mt][nt][1];
                float2 v1; v1.x = acc[mt][nt][2]; v1.y = acc[mt][nt][3];
                *reinterpret_cast<float2*>(Cf + (size_t)rbase*ldc + col)     = v0;
                *reinterpret_cast<float2*>(Cf + (size_t)(rbase+8)*ldc + col) = v1;
            }
        }
    }
}

// ---------------------------------------------------------------------------
// Depthwise causal conv (k=4) + bias + silu; half2 channels, TWO time-steps
// per thread (5 loads for 2 outputs instead of 8).
// ---------------------------------------------------------------------------
__global__ void __launch_bounds__(256) conv_kernel(
    const __half2* __restrict__ xz2,
    const float* __restrict__ cw, const float* __restrict__ cb,
    __half2* __restrict__ xc2)
{
    const int flat = blockIdx.x*256 + threadIdx.x;   // < 2*BB*(LL/2)*(DI/2)
    const int d2  = flat & (DI/2 - 1);
    const int tp  = (flat >> 9) & (LL/2 - 1);
    const int b   = (flat >> 18) & (BB-1);
    const int dir = flat >> 21;
    const int d   = d2*2;
    const int t0  = tp*2;

    const float4 wa = *reinterpret_cast<const float4*>(cw + d*4);
    const float4 wb = *reinterpret_cast<const float4*>(cw + d*4 + 4);
    const float cbx = cb[d], cby = cb[d+1];

    const __half2* src = xz2 + (size_t)b*LL*DI + d2;
    float2 v[5];
#pragma unroll
    for (int j=0;j<5;j++){
        const int tt = t0 - 3 + j;
        if (tt >= 0 && tt < LL){
            const int st = dir ? (LL-1-tt) : tt;
            v[j] = __half22float2(src[(size_t)st*DI]);
        } else {
            v[j].x = 0.f; v[j].y = 0.f;
        }
    }
    float o0x = cbx + wa.x*v[0].x + wa.y*v[1].x + wa.z*v[2].x + wa.w*v[3].x;
    float o0y = cby + wb.x*v[0].y + wb.y*v[1].y + wb.z*v[2].y + wb.w*v[3].y;
    float o1x = cbx + wa.x*v[1].x + wa.y*v[2].x + wa.z*v[3].x + wa.w*v[4].x;
    float o1y = cby + wb.x*v[1].y + wb.y*v[2].y + wb.z*v[3].y + wb.w*v[4].y;
    o0x = silu_fast(o0x); o0y = silu_fast(o0y);
    o1x = silu_fast(o1x); o1y = silu_fast(o1y);
    __half2* dst = xc2 + (size_t)dir*NT*(DI/2) + ((size_t)(b*LL+t0))*(DI/2) + d2;
    dst[0]      = __floats2half2_rn(o0x, o0y);
    dst[DI/2]   = __floats2half2_rn(o1x, o1y);
}

// ---------------------------------------------------------------------------
// Selective scan: 512 blocks x 64 threads (32 channels/block, 2 thr/channel).
// ---------------------------------------------------------------------------
#define TTILE 16
__global__ void __launch_bounds__(64) scan_kernel(
    const __half* __restrict__ xc,
    const float* __restrict__ xdbl, const __half* __restrict__ xz,
    const float* __restrict__ A_log,const float* __restrict__ Dp,
    const float* __restrict__ dtw,  const float* __restrict__ dtb,
    __half* __restrict__ yout)
{
    __shared__ float su [TTILE][32];
    __shared__ float sz [TTILE][32];
    __shared__ alignas(16) float sXD[TTILE][64];

    const int bx  = blockIdx.x;
    const int dir = bx >> 8;
    const int b   = (bx >> 5) & 7;
    const int dch = bx & 31;
    const int tid = threadIdx.x;
    const int c    = tid >> 1;
    const int half = tid & 1;
    const int d    = dch*32 + c;
    const int noff = half*8;

    float a[8], h[8];
#pragma unroll
    for (int j=0;j<8;j++){
        a[j] = -expf(A_log[(size_t)d*NSTATE + noff + j]);
        h[j] = 0.f;
    }
    const float a0 = -expf(A_log[(size_t)d*NSTATE]);
    unsigned ok = 1u;
#pragma unroll
    for (int j=0;j<8;j++){
        const float expect = a0*(float)(noff+j+1);
        ok &= (fabsf(a[j] - expect) <= 1e-4f*fabsf(a[j])) ? 1u : 0u;
    }
    ok &= __shfl_xor_sync(0xffffffffu, ok, 1);
    const bool fast = (ok != 0u);
    const float Dv = Dp[d];

    float w[16];
#pragma unroll
    for (int r=0;r<16;r++) w[r] = dtw[(size_t)d*RK + half*16 + r];
    const float bias = dtb[d];

    const size_t cb = (size_t)dir*NT*DI + (size_t)b*LL*DI + (size_t)dch*32;
    const __half* xcp = xc + cb;
    __half* yp = yout + cb;
    const float* xdp = xdbl + ((size_t)dir*NT + (size_t)b*LL)*64;
    const __half* zp = xz + (size_t)b*LL*(2*DI) + DI + (size_t)dch*32;

    for (int t0=0; t0<LL; t0+=TTILE){
        __syncthreads();
#pragma unroll
        for (int k=0;k<8;k++){
            const int idx = tid + k*64;
            const int row = idx>>5, col = idx&31;
            const int t = t0 + row;
            su [row][col] = __half2float(xcp[(size_t)t*DI + col]);
            const int zt = dir ? (LL-1-t) : t;
            sz [row][col] = __half2float(zp[(size_t)zt*(2*DI) + col]);
        }
#pragma unroll
        for (int k=0;k<16;k++){
            const int idx = tid + k*64;
            const int row = idx>>6, col = idx&63;
            sXD[row][col] = xdp[(size_t)(t0+row)*64 + col];
        }
        __syncthreads();

        float dtv[TTILE];
#pragma unroll
        for (int i=0;i<TTILE;i++){
            const float4* xr4 = reinterpret_cast<const float4*>(&sXD[i][half*16]);
            const float4 x0 = xr4[0], x1 = xr4[1], x2 = xr4[2], x3 = xr4[3];
            float s0 = x0.x*w[0]  + x1.x*w[4]  + x2.x*w[8]  + x3.x*w[12];
            float s1 = x0.y*w[1]  + x1.y*w[5]  + x2.y*w[9]  + x3.y*w[13];
            float s2 = x0.z*w[2]  + x1.z*w[6]  + x2.z*w[10] + x3.z*w[14];
            float s3 = x0.w*w[3]  + x1.w*w[7]  + x2.w*w[11] + x3.w*w[15];
            float v = (s0+s1)+(s2+s3);
            v += __shfl_xor_sync(0xffffffffu, v, 1);
            v += bias;
            dtv[i] = (v > 20.f) ? v : __logf(1.f + __expf(v));
        }

        if (fast){
#pragma unroll
            for (int i=0;i<TTILE;i++){
                const float dt  = dtv[i];
                const float u   = su[i][c];
                const float dtu = dt * u;
                const float4 B0 = *reinterpret_cast<const float4*>(&sXD[i][32+noff]);
                const float4 B1 = *reinterpret_cast<const float4*>(&sXD[i][36+noff]);
                const float4 C0 = *reinterpret_cast<const float4*>(&sXD[i][48+noff]);
                const float4 C1 = *reinterpret_cast<const float4*>(&sXD[i][52+noff]);
                const float Bv[8] = {B0.x,B0.y,B0.z,B0.w,B1.x,B1.y,B1.z,B1.w};
                const float Cv[8] = {C0.x,C0.y,C0.z,C0.w,C1.x,C1.y,C1.z,C1.w};
                const float rr  = __expf(dt * a0);
                const float r2 = rr*rr, r4 = r2*r2;
                const float r3 = r2*rr, r5 = r4*rr, r6 = r4*r2, r7 = r4*r3, r8 = r4*r4;
                const float base = half ? r8 : 1.f;
                const float p[8] = {base*rr, base*r2, base*r3, base*r4,
                                    base*r5, base*r6, base*r7, base*r8};
                float y0=0.f, y1=0.f;
#pragma unroll
                for (int j=0;j<8;j++){
                    h[j] = p[j]*h[j] + dtu * Bv[j];
                    const float cterm = h[j] * Cv[j];
                    if (j&1) y1 += cterm; else y0 += cterm;
                }
                float ys = y0 + y1;
                ys += __shfl_xor_sync(0xffffffffu, ys, 1);
                if (half==0){
                    const float y = (u*Dv + ys) * silu_fast(sz[i][c]);
                    yp[(size_t)(t0+i)*DI + c] = __float2half_rn(y);
                }
            }
        } else {
#pragma unroll
            for (int i=0;i<TTILE;i++){
                const float dt  = dtv[i];
                const float u   = su[i][c];
                const float dtu = dt * u;
                const float4 B0 = *reinterpret_cast<const float4*>(&sXD[i][32+noff]);
                const float4 B1 = *reinterpret_cast<const float4*>(&sXD[i][36+noff]);
                const float4 C0 = *reinterpret_cast<const float4*>(&sXD[i][48+noff]);
                const float4 C1 = *reinterpret_cast<const float4*>(&sXD[i][52+noff]);
                const float Bv[8] = {B0.x,B0.y,B0.z,B0.w,B1.x,B1.y,B1.z,B1.w};
                const float Cv[8] = {C0.x,C0.y,C0.z,C0.w,C1.x,C1.y,C1.z,C1.w};
                float y0=0.f, y1=0.f;
#pragma unroll
                for (int j=0;j<8;j++){
                    const float dA = __expf(dt * a[j]);
                    h[j] = dA*h[j] + dtu * Bv[j];
                    const float cterm = h[j] * Cv[j];
                    if (j&1) y1 += cterm; else y0 += cterm;
                }
                float ys = y0 + y1;
                ys += __shfl_xor_sync(0xffffffffu, ys, 1);
                if (half==0){
                    const float y = (u*Dv + ys) * silu_fast(sz[i][c]);
                    yp[(size_t)(t0+i)*DI + c] = __float2half_rn(y);
                }
            }
        }
    }
}

// ---------------------------------------------------------------------------
// Final output: hidden[b,t,:] = o_fwd[b,t,:] + o_bwd[b,L-1-t,:]  (fp16 -> fp32)
// ---------------------------------------------------------------------------
__global__ void __launch_bounds__(256) add_kernel(
    const __half* __restrict__ o, float* __restrict__ dst)
{
    const int flat = blockIdx.x*256 + threadIdx.x;
    const int e = flat & (DM-1);
    const int t = (flat >> 9) & (LL-1);
    const int b = flat >> 19;
    const int tok  = b*LL + t;
    const int tokb = b*LL + (LL-1-t);
    dst[flat] = __half2float(o[(size_t)tok*DM + e])
              + __half2float(o[(size_t)(NT + tokb)*DM + e]);
}

// ---------------------------------------------------------------------------
// Launch
// ---------------------------------------------------------------------------
extern "C" void kernel_launch(void* const* d_in, const int* in_sizes, int n_in,
                              void* d_out, int out_size)
{
    (void)in_sizes; (void)n_in; (void)out_size;
    const float* x      = (const float*)d_in[0];
    const float* norm_w = (const float*)d_in[1];
    const float* norm_b = (const float*)d_in[2];
    const float* in_w   = (const float*)d_in[3];
    const float* conv_w = (const float*)d_in[4];
    const float* conv_b = (const float*)d_in[5];
    const float* xp_w   = (const float*)d_in[6];
    const float* dtp_w  = (const float*)d_in[7];
    const float* dtp_b  = (const float*)d_in[8];
    const float* A_log  = (const float*)d_in[9];
    const float* Dp     = (const float*)d_in[10];
    const float* out_w  = (const float*)d_in[11];
    float* dout = (float*)d_out;

    float *resid,*xdbl;
    __half *hbuf,*xzb,*xcb,*yb,*ob,*w1,*w2,*w4;
    cudaGetSymbolAddress((void**)&resid, g_resid);
    cudaGetSymbolAddress((void**)&xzb,   g_xz);
    cudaGetSymbolAddress((void**)&xdbl,  g_xdbl);
    cudaGetSymbolAddress((void**)&ob,    g_o);
    cudaGetSymbolAddress((void**)&hbuf,  g_h);
    cudaGetSymbolAddress((void**)&xcb,   g_xc);
    cudaGetSymbolAddress((void**)&yb,    g_y);
    cudaGetSymbolAddress((void**)&w1,    g_w1);
    cudaGetSymbolAddress((void**)&w2,    g_w2);
    cudaGetSymbolAddress((void**)&w4,    g_w4);

    constexpr int SMEM_BIG = 6*(128*64 + 128*64);   // 98304 (128x128, 6 stages)
    constexpr int SMEM_SML = 4*(64*64 + 64*64);     // 32768 (64x64, 4 stages)
    static bool attr_done = false;
    if (!attr_done){
        cudaFuncSetAttribute((const void*)gemm_f16_kernel<128,128,6,__half>,
                             cudaFuncAttributeMaxDynamicSharedMemorySize, SMEM_BIG);
        cudaFuncSetAttribute((const void*)gemm_f16_kernel<64,64,4,float>,
                             cudaFuncAttributeMaxDynamicSharedMemorySize, SMEM_SML);
        attr_done = true;
    }

    // weight conversion
    {
        const int n1 = DEPTH*2*DI*DM/4, n2 = DEPTH*64*DI/4, n4 = DEPTH*DM*DI/4;
        wcvt_kernel<<<(n1+255)/256,256>>>(in_w,  w1, n1);
        wcvt_kernel<<<(n2+255)/256,256>>>(xp_w,  w2, n2);
        wcvt_kernel<<<(n4+255)/256,256>>>(out_w, w4, n4);
    }

    for (int i=0;i<DEPTH;i++){
        ln_kernel<<<NT,128>>>( (i==0)? x : resid, (i==0)? (const __half*)nullptr : ob,
                               resid, norm_w + i*DM, norm_b + i*DM, hbuf );

        // GEMM1: xz[8192,2048] = h @ in_w^T   (fp16 out)
        gemm_f16_kernel<128,128,6,__half><<<dim3(2048/128, 8192/128), 128, SMEM_BIG>>>(
            hbuf, DM, w1 + (size_t)i*2*DI*DM, DM, xzb, 2*DI);

        // conv: 2 time-steps per thread
        conv_kernel<<<(2*BB*(LL/2)*(DI/2))/256,256>>>(
            reinterpret_cast<const __half2*>(xzb), conv_w + i*DI*4, conv_b + i*DI,
            reinterpret_cast<__half2*>(xcb));

        // GEMM2: xdbl[16384,64] = xc @ xp_w^T   (fp32 out)
        gemm_f16_kernel<64,64,4,float><<<dim3(1, 16384/64), 128, SMEM_SML>>>(
            xcb, DI, w2 + (size_t)i*64*DI, DI, xdbl, 64);

        scan_kernel<<<512,64>>>(xcb, xdbl, xzb,
                                 A_log + (size_t)i*DI*NSTATE, Dp + i*DI,
                                 dtp_w + (size_t)i*DI*RK, dtp_b + i*DI, yb);

        // GEMM4: o[16384,512] = y @ out_w^T   (fp16 out)
        gemm_f16_kernel<128,128,6,__half><<<dim3(512/128, 16384/128), 128, SMEM_BIG>>>(
            yb, DI, w4 + (size_t)i*DM*DI, DI, ob, DM);
    }
    add_kernel<<<(NT*DM)/256,256>>>(ob, dout);
}

// round 17
// speedup vs baseline: 1.0776x; 1.0776x over previous
#include <cuda_runtime.h>
#include <cuda_fp16.h>
#include <cstdint>
#include <cstddef>

// ---------------------------------------------------------------------------
// Problem constants
// ---------------------------------------------------------------------------
#define BB      8
#define LL      1024
#define DM      512
#define DI      1024
#define NSTATE  16
#define RK      32
#define NT      (BB*LL)          // 8192 tokens
#define DEPTH   4

// ---------------------------------------------------------------------------
// Scratch buffers
// ---------------------------------------------------------------------------
__device__ float  g_resid[NT*DM];
__device__ __half g_h    [NT*DM];
__device__ __half g_xz   [NT*2*DI];
__device__ __half g_xc   [2*NT*DI];
__device__ float  g_xdbl [2*NT*64];
__device__ __half g_y    [2*NT*DI];
__device__ __half g_o    [2*NT*DM];
__device__ __half g_w1[DEPTH*2*DI*DM];
__device__ __half g_w2[DEPTH*64*DI];
__device__ __half g_w4[DEPTH*DM*DI];

// ---------------------------------------------------------------------------
// Helpers
// ---------------------------------------------------------------------------
__device__ __forceinline__ uint32_t smem_u32(const void* p){
    uint32_t a;
    asm("{ .reg .u64 t; cvta.to.shared.u64 t, %1; cvt.u32.u64 %0, t; }" : "=r"(a) : "l"(p));
    return a;
}
__device__ __forceinline__ float warpReduceSum(float v){
#pragma unroll
    for (int o=16;o>0;o>>=1) v += __shfl_xor_sync(0xffffffffu, v, o);
    return v;
}
__device__ __forceinline__ float silu_fast(float x){
    return x / (1.f + __expf(-x));
}
__device__ __forceinline__ void ldm_x4(uint32_t* r, uint32_t addr){
    asm volatile("ldmatrix.sync.aligned.m8n8.x4.shared.b16 {%0,%1,%2,%3}, [%4];"
        : "=r"(r[0]), "=r"(r[1]), "=r"(r[2]), "=r"(r[3]) : "r"(addr));
}
__device__ __forceinline__ void mma_f16(float* c, const uint32_t* a, const uint32_t* b){
    asm volatile(
        "mma.sync.aligned.m16n8k16.row.col.f32.f16.f16.f32 "
        "{%0,%1,%2,%3}, {%4,%5,%6,%7}, {%8,%9}, {%0,%1,%2,%3};"
        : "+f"(c[0]), "+f"(c[1]), "+f"(c[2]), "+f"(c[3])
        : "r"(a[0]), "r"(a[1]), "r"(a[2]), "r"(a[3]), "r"(b[0]), "r"(b[1]));
}
__device__ __forceinline__ void cp_async16(uint32_t dst, const void* src){
    asm volatile("cp.async.cg.shared.global [%0], [%1], 16;" :: "r"(dst), "l"(src));
}
__device__ __forceinline__ void cp_commit(){
    asm volatile("cp.async.commit_group;");
}
template<int N>
__device__ __forceinline__ void cp_wait(){
    asm volatile("cp.async.wait_group %0;" :: "n"(N));
}
__device__ __forceinline__ uint32_t pack_h2(__half a, __half b){
    __half2 h = __halves2half2(a, b);
    return *reinterpret_cast<uint32_t*>(&h);
}
__device__ __forceinline__ uint32_t swz(int r, int q){
    return (uint32_t)(r*64 + ((q ^ ((r>>1)&3))<<4));
}

// ---------------------------------------------------------------------------
// Weight conversion (two launches total so GEMM1 is the 4th kernel in graph)
// ---------------------------------------------------------------------------
__global__ void __launch_bounds__(256) wcvt_kernel(
    const float* __restrict__ src, __half* __restrict__ dst, int n4)
{
    const int i = blockIdx.x*256 + threadIdx.x;
    if (i >= n4) return;
    float4 v = reinterpret_cast<const float4*>(src)[i];
    uint2 o;
    o.x = pack_h2(__float2half_rn(v.x), __float2half_rn(v.y));
    o.y = pack_h2(__float2half_rn(v.z), __float2half_rn(v.w));
    reinterpret_cast<uint2*>(dst)[i] = o;
}
__global__ void __launch_bounds__(256) wcvt2_kernel(
    const float* __restrict__ s2, const float* __restrict__ s4,
    __half* __restrict__ d2, __half* __restrict__ d4, int n2, int n4)
{
    int i = blockIdx.x*256 + threadIdx.x;
    const float* s; __half* d; int off;
    if (i < n2){ s = s2; d = d2; off = i; }
    else if (i < n2+n4){ s = s4; d = d4; off = i-n2; }
    else return;
    float4 v = reinterpret_cast<const float4*>(s)[off];
    uint2 o;
    o.x = pack_h2(__float2half_rn(v.x), __float2half_rn(v.y));
    o.y = pack_h2(__float2half_rn(v.z), __float2half_rn(v.w));
    reinterpret_cast<uint2*>(d)[off] = o;
}

// ---------------------------------------------------------------------------
// LayerNorm + residual (+ fused bidirectional add of fp16 o); h as fp16.
// ---------------------------------------------------------------------------
__global__ void __launch_bounds__(128) ln_kernel(
    const float* __restrict__ src0, const __half* __restrict__ o,
    float* __restrict__ resid,
    const float* __restrict__ w, const float* __restrict__ b,
    __half* __restrict__ hout)
{
    __shared__ float sm[8];
    const int row = blockIdx.x, tid = threadIdx.x;
    float4 v = reinterpret_cast<const float4*>(src0 + (size_t)row*DM)[tid];
    if (o){
        const int t    = row & (LL-1);
        const int tokb = (row - t) + (LL-1 - t);
        uint2 a1 = reinterpret_cast<const uint2*>(o + (size_t)row*DM)[tid];
        uint2 a2 = reinterpret_cast<const uint2*>(o + (size_t)(NT + tokb)*DM)[tid];
        float2 f10 = __half22float2(*reinterpret_cast<__half2*>(&a1.x));
        float2 f11 = __half22float2(*reinterpret_cast<__half2*>(&a1.y));
        float2 f20 = __half22float2(*reinterpret_cast<__half2*>(&a2.x));
        float2 f21 = __half22float2(*reinterpret_cast<__half2*>(&a2.y));
        v.x += f10.x+f20.x; v.y += f10.y+f20.y;
        v.z += f11.x+f21.x; v.w += f11.y+f21.y;
    }
    reinterpret_cast<float4*>(resid + (size_t)row*DM)[tid] = v;

    float s = v.x+v.y+v.z+v.w;
    s = warpReduceSum(s);
    const int wid = tid>>5, lane = tid&31;
    if (lane==0) sm[wid]=s;
    __syncthreads();
    const float mu = (sm[0]+sm[1]+sm[2]+sm[3]) * (1.f/(float)DM);
    const float dx=v.x-mu, dy=v.y-mu, dz=v.z-mu, dw=v.w-mu;
    float q = dx*dx+dy*dy+dz*dz+dw*dw;
    q = warpReduceSum(q);
    if (lane==0) sm[4+wid]=q;
    __syncthreads();
    const float var = (sm[4]+sm[5]+sm[6]+sm[7]) * (1.f/(float)DM);
    const float rs = rsqrtf(var + 1e-5f);
    const float4 wv = reinterpret_cast<const float4*>(w)[tid];
    const float4 bv = reinterpret_cast<const float4*>(b)[tid];
    float4 ov;
    ov.x = dx*rs*wv.x + bv.x;
    ov.y = dy*rs*wv.y + bv.y;
    ov.z = dz*rs*wv.z + bv.z;
    ov.w = dw*rs*wv.w + bv.w;
    uint2 H;
    H.x = pack_h2(__float2half_rn(ov.x), __float2half_rn(ov.y));
    H.y = pack_h2(__float2half_rn(ov.z), __float2half_rn(ov.w));
    reinterpret_cast<uint2*>(hout + (size_t)row*DM)[tid] = H;
}

// ---------------------------------------------------------------------------
// fp16 MMA GEMM: C = A @ W^T. 128 threads, 4 warps 2x2, warp (BM/2)x(BN/2).
// 4-stage cp.async ring (3-chunk prefetch), one barrier per chunk.  (best cfg)
// ---------------------------------------------------------------------------
template<int BM,int BN,typename OT>
__global__ void __launch_bounds__(128) gemm_f16_kernel(
    const __half* __restrict__ A, int lda,
    const __half* __restrict__ W, int K,
    OT* __restrict__ C, int ldc)
{
    constexpr int WM  = BM/2;
    constexpr int WN  = BN/2;
    constexpr int MT  = WM/16;
    constexpr int NTL = WN/8;
    constexpr int BOF = BM*64;
    constexpr int STAGE = BM*64 + BN*64;

    extern __shared__ __align__(16) char smem[];
    const uint32_t sb = smem_u32(smem);

    const int tid  = threadIdx.x;
    const int wid  = tid>>5, lane = tid&31;
    const int m0   = blockIdx.y*BM, n0 = blockIdx.x*BN;
    const int wm0  = (wid>>1)*WM;
    const int wn0  = (wid&1)*WN;

    float acc[MT][NTL][4];
#pragma unroll
    for (int i=0;i<MT;i++)
#pragma unroll
        for (int j=0;j<NTL;j++)
#pragma unroll
            for (int q=0;q<4;q++) acc[i][j][q]=0.f;

    const int a_row = (lane&7) + ((lane>>3)&1)*8;
    const int aq    = lane>>4;
    const int b_row = (lane&7) + (lane>>4)*8;
    const int bq    = (lane>>3)&1;

    auto issue_stage = [&](int s, int k0){
        const uint32_t base = sb + (uint32_t)(s*STAGE);
#pragma unroll
        for (int u=0; u<BM/32; ++u){
            const int id = tid + u*128;
            const int r = id>>2, q = id&3;
            cp_async16(base + swz(r,q), A + (size_t)(m0+r)*lda + k0 + q*8);
        }
#pragma unroll
        for (int u=0; u<BN/32; ++u){
            const int id = tid + u*128;
            const int r = id>>2, q = id&3;
            cp_async16(base + BOF + swz(r,q), W + (size_t)(n0+r)*K + k0 + q*8);
        }
        cp_commit();
    };

    const int nchunk = K >> 5;
    issue_stage(0, 0);
    issue_stage(1, 32);
    issue_stage(2, 64);

    for (int c=0; c<nchunk; ++c){
        const int rem = nchunk-1-c;
        if (rem >= 2) cp_wait<2>(); else if (rem == 1) cp_wait<1>(); else cp_wait<0>();
        __syncthreads();
        if (c+3 < nchunk) issue_stage((c+3)&3, (c+3)*32);

        const uint32_t sbs = sb + (uint32_t)((c&3)*STAGE);
#pragma unroll
        for (int ks=0; ks<2; ++ks){
            uint32_t ah[MT][4];
#pragma unroll
            for (int mt=0; mt<MT; ++mt){
                const int row = wm0 + mt*16 + a_row;
                ldm_x4(ah[mt], sbs + swz(row, ks*2 + aq));
            }
            uint32_t bh[NTL][2];
#pragma unroll
            for (int tp=0; tp<NTL/2; ++tp){
                const int row = wn0 + tp*16 + b_row;
                uint32_t t4[4];
                ldm_x4(t4, sbs + BOF + swz(row, ks*2 + bq));
                bh[tp*2][0]=t4[0]; bh[tp*2][1]=t4[1];
                bh[tp*2+1][0]=t4[2]; bh[tp*2+1][1]=t4[3];
            }
#pragma unroll
            for (int mt=0; mt<MT; ++mt)
#pragma unroll
                for (int nt=0; nt<NTL; ++nt)
                    mma_f16(acc[mt][nt], ah[mt], bh[nt]);
        }
    }

    const int cr = lane>>2;
    const int cc = (lane&3)*2;
#pragma unroll
    for (int mt=0; mt<MT; ++mt){
        const int rbase = m0 + wm0 + mt*16 + cr;
#pragma unroll
        for (int nt=0; nt<NTL; ++nt){
            const int col = n0 + wn0 + nt*8 + cc;
            if (sizeof(OT) == 2){
                __half* Ch = reinterpret_cast<__half*>(C);
                uint32_t p0 = pack_h2(__float2half_rn(acc[mt][nt][0]),
                                      __float2half_rn(acc[mt][nt][1]));
                uint32_t p1 = pack_h2(__float2half_rn(acc[mt][nt][2]),
                                      __float2half_rn(acc[mt][nt][3]));
                *reinterpret_cast<uint32_t*>(Ch + (size_t)rbase*ldc + col)     = p0;
                *reinterpret_cast<uint32_t*>(Ch + (size_t)(rbase+8)*ldc + col) = p1;
            } else {
                float* Cf = reinterpret_cast<float*>(C);
                float2 v0; v0.x = acc[mt][nt][0]; v0.y = acc[mt][nt][1];
                float2 v1; v1.x = acc[mt][nt][2]; v1.y = acc[mt][nt][3];
                *reinterpret_cast<float2*>(Cf + (size_t)rbase*ldc + col)     = v0;
                *reinterpret_cast<float2*>(Cf + (size_t)(rbase+8)*ldc + col) = v1;
            }
        }
    }
}

// ---------------------------------------------------------------------------
// Depthwise causal conv (k=4) + bias + silu; half2 channels, TWO time-steps
// per thread (5 loads for 2 outputs).
// ---------------------------------------------------------------------------
__global__ void __launch_bounds__(256) conv_kernel(
    const __half2* __restrict__ xz2,
    const float* __restrict__ cw, const float* __restrict__ cb,
    __half2* __restrict__ xc2)
{
    const int flat = blockIdx.x*256 + threadIdx.x;
    const int d2  = flat & (DI/2 - 1);
    const int tp  = (flat >> 9) & (LL/2 - 1);
    const int b   = (flat >> 18) & (BB-1);
    const int dir = flat >> 21;
    const int d   = d2*2;
    const int t0  = tp*2;

    const float4 wa = *reinterpret_cast<const float4*>(cw + d*4);
    const float4 wb = *reinterpret_cast<const float4*>(cw + d*4 + 4);
    const float cbx = cb[d], cby = cb[d+1];

    const __half2* src = xz2 + (size_t)b*LL*DI + d2;
    float2 v[5];
#pragma unroll
    for (int j=0;j<5;j++){
        const int tt = t0 - 3 + j;
        if (tt >= 0 && tt < LL){
            const int st = dir ? (LL-1-tt) : tt;
            v[j] = __half22float2(src[(size_t)st*DI]);
        } else {
            v[j].x = 0.f; v[j].y = 0.f;
        }
    }
    float o0x = cbx + wa.x*v[0].x + wa.y*v[1].x + wa.z*v[2].x + wa.w*v[3].x;
    float o0y = cby + wb.x*v[0].y + wb.y*v[1].y + wb.z*v[2].y + wb.w*v[3].y;
    float o1x = cbx + wa.x*v[1].x + wa.y*v[2].x + wa.z*v[3].x + wa.w*v[4].x;
    float o1y = cby + wb.x*v[1].y + wb.y*v[2].y + wb.z*v[3].y + wb.w*v[4].y;
    o0x = silu_fast(o0x); o0y = silu_fast(o0y);
    o1x = silu_fast(o1x); o1y = silu_fast(o1y);
    __half2* dst = xc2 + (size_t)dir*NT*(DI/2) + ((size_t)(b*LL+t0))*(DI/2) + d2;
    dst[0]      = __floats2half2_rn(o0x, o0y);
    dst[DI/2]   = __floats2half2_rn(o1x, o1y);
}

// ---------------------------------------------------------------------------
// Selective scan: 512 blocks x 64 threads, 2 thr/channel, fused dt proj.
// NEW: double-buffered cp.async tile prefetch — next tile's gmem loads
// overlap the current tile's recurrence.
// ---------------------------------------------------------------------------
#define TTILE 16
#define NTILES (LL/TTILE)
__global__ void __launch_bounds__(64) scan_kernel(
    const __half* __restrict__ xc,
    const float* __restrict__ xdbl, const __half* __restrict__ xz,
    const float* __restrict__ A_log,const float* __restrict__ Dp,
    const float* __restrict__ dtw,  const float* __restrict__ dtb,
    __half* __restrict__ yout)
{
    __shared__ __align__(16) __half suh[2][TTILE][32];
    __shared__ __align__(16) __half szh[2][TTILE][32];
    __shared__ __align__(16) float  sXD[2][TTILE][64];

    const int bx  = blockIdx.x;
    const int dir = bx >> 8;
    const int b   = (bx >> 5) & 7;
    const int dch = bx & 31;
    const int tid = threadIdx.x;
    const int c    = tid >> 1;
    const int half = tid & 1;
    const int d    = dch*32 + c;
    const int noff = half*8;

    float a[8], h[8];
#pragma unroll
    for (int j=0;j<8;j++){
        a[j] = -expf(A_log[(size_t)d*NSTATE + noff + j]);
        h[j] = 0.f;
    }
    const float a0 = -expf(A_log[(size_t)d*NSTATE]);
    unsigned ok = 1u;
#pragma unroll
    for (int j=0;j<8;j++){
        const float expect = a0*(float)(noff+j+1);
        ok &= (fabsf(a[j] - expect) <= 1e-4f*fabsf(a[j])) ? 1u : 0u;
    }
    ok &= __shfl_xor_sync(0xffffffffu, ok, 1);
    const bool fast = (ok != 0u);
    const float Dv = Dp[d];

    float w[16];
#pragma unroll
    for (int r=0;r<16;r++) w[r] = dtw[(size_t)d*RK + half*16 + r];
    const float bias = dtb[d];

    const size_t cb = (size_t)dir*NT*DI + (size_t)b*LL*DI + (size_t)dch*32;
    const __half* xcp = xc + cb;
    __half* yp = yout + cb;
    const float* xdp = xdbl + ((size_t)dir*NT + (size_t)b*LL)*64;
    const __half* zp = xz + (size_t)b*LL*(2*DI) + DI + (size_t)dch*32;

    const uint32_t su_b = smem_u32(&suh[0][0][0]);
    const uint32_t sz_b = smem_u32(&szh[0][0][0]);
    const uint32_t xd_b = smem_u32(&sXD[0][0][0]);
    const int lrow = tid>>2, lq = tid&3;     // su/sz: 1 chunk per thread

    auto issue_tile = [&](int buf, int t0){
        // su: 16 rows x 64B; one 16B chunk per thread
        cp_async16(su_b + (uint32_t)(buf*TTILE*64 + lrow*64 + lq*16),
                   xcp + (size_t)(t0+lrow)*DI + lq*8);
        // sz: time-flipped row index for dir=1
        const int zt = dir ? (LL-1-(t0+lrow)) : (t0+lrow);
        cp_async16(sz_b + (uint32_t)(buf*TTILE*64 + lrow*64 + lq*16),
                   zp + (size_t)zt*(2*DI) + lq*8);
        // sXD: 16 rows x 256B; 4 chunks per thread
#pragma unroll
        for (int k=0;k<4;k++){
            const int idx = tid + k*64;
            const int row = idx>>4, q = idx&15;
            cp_async16(xd_b + (uint32_t)(buf*TTILE*256 + row*256 + q*16),
                       xdp + (size_t)(t0+row)*64 + q*4);
        }
        cp_commit();
    };

    issue_tile(0, 0);

    for (int tt=0; tt<NTILES; ++tt){
        const int t0 = tt*TTILE;
        const int buf = tt & 1;
        if (tt+1 < NTILES){
            issue_tile(buf^1, t0+TTILE);
            cp_wait<1>();
        } else {
            cp_wait<0>();
        }
        __syncthreads();

        float dtv[TTILE];
#pragma unroll
        for (int i=0;i<TTILE;i++){
            const float4* xr4 = reinterpret_cast<const float4*>(&sXD[buf][i][half*16]);
            const float4 x0 = xr4[0], x1 = xr4[1], x2 = xr4[2], x3 = xr4[3];
            float s0 = x0.x*w[0]  + x1.x*w[4]  + x2.x*w[8]  + x3.x*w[12];
            float s1 = x0.y*w[1]  + x1.y*w[5]  + x2.y*w[9]  + x3.y*w[13];
            float s2 = x0.z*w[2]  + x1.z*w[6]  + x2.z*w[10] + x3.z*w[14];
            float s3 = x0.w*w[3]  + x1.w*w[7]  + x2.w*w[11] + x3.w*w[15];
            float v = (s0+s1)+(s2+s3);
            v += __shfl_xor_sync(0xffffffffu, v, 1);
            v += bias;
            dtv[i] = (v > 20.f) ? v : __logf(1.f + __expf(v));
        }

        if (fast){
#pragma unroll
            for (int i=0;i<TTILE;i++){
                const float dt  = dtv[i];
                const float u   = __half2float(suh[buf][i][c]);
                const float dtu = dt * u;
                const float4 B0 = *reinterpret_cast<const float4*>(&sXD[buf][i][32+noff]);
                const float4 B1 = *reinterpret_cast<const float4*>(&sXD[buf][i][36+noff]);
                const float4 C0 = *reinterpret_cast<const float4*>(&sXD[buf][i][48+noff]);
                const float4 C1 = *reinterpret_cast<const float4*>(&sXD[buf][i][52+noff]);
                const float Bv[8] = {B0.x,B0.y,B0.z,B0.w,B1.x,B1.y,B1.z,B1.w};
                const float Cv[8] = {C0.x,C0.y,C0.z,C0.w,C1.x,C1.y,C1.z,C1.w};
                const float rr  = __expf(dt * a0);
                const float r2 = rr*rr, r4 = r2*r2;
                const float r3 = r2*rr, r5 = r4*rr, r6 = r4*r2, r7 = r4*r3, r8 = r4*r4;
                const float base = half ? r8 : 1.f;
                const float p[8] = {base*rr, base*r2, base*r3, base*r4,
                                    base*r5, base*r6, base*r7, base*r8};
                float y0=0.f, y1=0.f;
#pragma unroll
                for (int j=0;j<8;j++){
                    h[j] = p[j]*h[j] + dtu * Bv[j];
                    const float cterm = h[j] * Cv[j];
                    if (j&1) y1 += cterm; else y0 += cterm;
                }
                float ys = y0 + y1;
                ys += __shfl_xor_sync(0xffffffffu, ys, 1);
                if (half==0){
                    const float z = __half2float(szh[buf][i][c]);
                    const float y = (u*Dv + ys) * silu_fast(z);
                    yp[(size_t)(t0+i)*DI + c] = __float2half_rn(y);
                }
            }
        } else {
#pragma unroll
            for (int i=0;i<TTILE;i++){
                const float dt  = dtv[i];
                const float u   = __half2float(suh[buf][i][c]);
                const float dtu = dt * u;
                const float4 B0 = *reinterpret_cast<const float4*>(&sXD[buf][i][32+noff]);
                const float4 B1 = *reinterpret_cast<const float4*>(&sXD[buf][i][36+noff]);
                const float4 C0 = *reinterpret_cast<const float4*>(&sXD[buf][i][48+noff]);
                const float4 C1 = *reinterpret_cast<const float4*>(&sXD[buf][i][52+noff]);
                const float Bv[8] = {B0.x,B0.y,B0.z,B0.w,B1.x,B1.y,B1.z,B1.w};
                const float Cv[8] = {C0.x,C0.y,C0.z,C0.w,C1.x,C1.y,C1.z,C1.w};
                float y0=0.f, y1=0.f;
#pragma unroll
                for (int j=0;j<8;j++){
                    const float dA = __expf(dt * a[j]);
                    h[j] = dA*h[j] + dtu * Bv[j];
                    const float cterm = h[j] * Cv[j];
                    if (j&1) y1 += cterm; else y0 += cterm;
                }
                float ys = y0 + y1;
                ys += __shfl_xor_sync(0xffffffffu, ys, 1);
                if (half==0){
                    const float z = __half2float(szh[buf][i][c]);
                    const float y = (u*Dv + ys) * silu_fast(z);
                    yp[(size_t)(t0+i)*DI + c] = __float2half_rn(y);
                }
            }
        }
        __syncthreads();   // buffer free before iter tt+1 overwrites buf^1
    }
}

// ---------------------------------------------------------------------------
// Final output: hidden[b,t,:] = o_fwd[b,t,:] + o_bwd[b,L-1-t,:]  (fp16 -> fp32)
// ---------------------------------------------------------------------------
__global__ void __launch_bounds__(256) add_kernel(
    const __half* __restrict__ o, float* __restrict__ dst)
{
    const int flat = blockIdx.x*256 + threadIdx.x;
    const int e = flat & (DM-1);
    const int t = (flat >> 9) & (LL-1);
    const int b = flat >> 19;
    const int tok  = b*LL + t;
    const int tokb = b*LL + (LL-1-t);
    dst[flat] = __half2float(o[(size_t)tok*DM + e])
              + __half2float(o[(size_t)(NT + tokb)*DM + e]);
}

// ---------------------------------------------------------------------------
// Launch
// ---------------------------------------------------------------------------
extern "C" void kernel_launch(void* const* d_in, const int* in_sizes, int n_in,
                              void* d_out, int out_size)
{
    (void)in_sizes; (void)n_in; (void)out_size;
    const float* x      = (const float*)d_in[0];
    const float* norm_w = (const float*)d_in[1];
    const float* norm_b = (const float*)d_in[2];
    const float* in_w   = (const float*)d_in[3];
    const float* conv_w = (const float*)d_in[4];
    const float* conv_b = (const float*)d_in[5];
    const float* xp_w   = (const float*)d_in[6];
    const float* dtp_w  = (const float*)d_in[7];
    const float* dtp_b  = (const float*)d_in[8];
    const float* A_log  = (const float*)d_in[9];
    const float* Dp     = (const float*)d_in[10];
    const float* out_w  = (const float*)d_in[11];
    float* dout = (float*)d_out;

    float *resid,*xdbl;
    __half *hbuf,*xzb,*xcb,*yb,*ob,*w1,*w2,*w4;
    cudaGetSymbolAddress((void**)&resid, g_resid);
    cudaGetSymbolAddress((void**)&xzb,   g_xz);
    cudaGetSymbolAddress((void**)&xdbl,  g_xdbl);
    cudaGetSymbolAddress((void**)&ob,    g_o);
    cudaGetSymbolAddress((void**)&hbuf,  g_h);
    cudaGetSymbolAddress((void**)&xcb,   g_xc);
    cudaGetSymbolAddress((void**)&yb,    g_y);
    cudaGetSymbolAddress((void**)&w1,    g_w1);
    cudaGetSymbolAddress((void**)&w2,    g_w2);
    cudaGetSymbolAddress((void**)&w4,    g_w4);

    constexpr int SMEM_BIG = 4*(128*64 + 128*64);   // 65536 (128x128, 4 stages)
    constexpr int SMEM_SML = 4*(64*64 + 64*64);     // 32768 (64x64, 4 stages)
    static bool attr_done = false;
    if (!attr_done){
        cudaFuncSetAttribute((const void*)gemm_f16_kernel<128,128,__half>,
                             cudaFuncAttributeMaxDynamicSharedMemorySize, SMEM_BIG);
        cudaFuncSetAttribute((const void*)gemm_f16_kernel<64,64,float>,
                             cudaFuncAttributeMaxDynamicSharedMemorySize, SMEM_SML);
        attr_done = true;
    }

    // weight conversion: exactly 2 launches -> GEMM1 is the 4th kernel
    {
        const int n1 = DEPTH*2*DI*DM/4, n2 = DEPTH*64*DI/4, n4 = DEPTH*DM*DI/4;
        wcvt_kernel<<<(n1+255)/256,256>>>(in_w, w1, n1);
        wcvt2_kernel<<<(n2+n4+255)/256,256>>>(xp_w, out_w, w2, w4, n2, n4);
    }

    for (int i=0;i<DEPTH;i++){
        ln_kernel<<<NT,128>>>( (i==0)? x : resid, (i==0)? (const __half*)nullptr : ob,
                               resid, norm_w + i*DM, norm_b + i*DM, hbuf );

        // GEMM1: xz[8192,2048] = h @ in_w^T   (fp16 out)
        gemm_f16_kernel<128,128,__half><<<dim3(2048/128, 8192/128), 128, SMEM_BIG>>>(
            hbuf, DM, w1 + (size_t)i*2*DI*DM, DM, xzb, 2*DI);

        // conv: 2 time-steps per thread
        conv_kernel<<<(2*BB*(LL/2)*(DI/2))/256,256>>>(
            reinterpret_cast<const __half2*>(xzb), conv_w + i*DI*4, conv_b + i*DI,
            reinterpret_cast<__half2*>(xcb));

        // GEMM2: xdbl[16384,64] = xc @ xp_w^T   (fp32 out)
        gemm_f16_kernel<64,64,float><<<dim3(1, 16384/64), 128, SMEM_SML>>>(
            xcb, DI, w2 + (size_t)i*64*DI, DI, xdbl, 64);

        scan_kernel<<<512,64>>>(xcb, xdbl, xzb,
                                 A_log + (size_t)i*DI*NSTATE, Dp + i*DI,
                                 dtp_w + (size_t)i*DI*RK, dtp_b + i*DI, yb);

        // GEMM4: o[16384,512] = y @ out_w^T   (fp16 out)
        gemm_f16_kernel<128,128,__half><<<dim3(512/128, 16384/128), 128, SMEM_BIG>>>(
            yb, DI, w4 + (size_t)i*DM*DI, DI, ob, DM);
    }
    add_kernel<<<(NT*DM)/256,256>>>(ob, dout);
}